// round 15
// baseline (speedup 1.0000x reference)
#include <cuda_runtime.h>
#include <cuda_fp16.h>
#include <cstdint>

#define N_TOKENS 16384
#define HIDDEN   4096
#define NE       192   // 3 * 64 experts
#define E        64
#define LOG2E    1.4426950408889634f
#define WSCALE   64.0f
#define INV_WSCALE (1.0f / 64.0f)

// ---------------- scratch ----------------------------------------------------
__device__ __half g_w[NE * HIDDEN];   // fp16(W * 64)

// ---------------- helpers ----------------------------------------------------
__device__ __forceinline__ uint32_t smem_u32(const void* p) {
    uint32_t a;
    asm("{ .reg .u64 t; cvta.to.shared.u64 t, %1; cvt.u32.u64 %0, t; }" : "=r"(a) : "l"(p));
    return a;
}
__device__ __forceinline__ void sts64(uint32_t addr, uint32_t a, uint32_t b) {
    asm volatile("st.shared.v2.b32 [%0], {%1, %2};" :: "r"(addr), "r"(a), "r"(b));
}
__device__ __forceinline__ void cp_async16(uint32_t dst, const void* src) {
    asm volatile("cp.async.cg.shared.global [%0], [%1], 16;" :: "r"(dst), "l"(src));
}
__device__ __forceinline__ void cp_commit() {
    asm volatile("cp.async.commit_group;" ::: "memory");
}
template <int N>
__device__ __forceinline__ void cp_wait() {
    asm volatile("cp.async.wait_group %0;" :: "n"(N) : "memory");
}
__device__ __forceinline__ void bar_sync(int id) {
    asm volatile("bar.sync %0, 640;" :: "r"(id) : "memory");
}
__device__ __forceinline__ void bar_arrive(int id) {
    asm volatile("bar.arrive %0, 640;" :: "r"(id) : "memory");
}
__device__ __forceinline__ void ldmatrix_x4(uint32_t* r, uint32_t addr) {
    asm volatile("ldmatrix.sync.aligned.m8n8.x4.shared.b16 {%0,%1,%2,%3}, [%4];"
                 : "=r"(r[0]), "=r"(r[1]), "=r"(r[2]), "=r"(r[3]) : "r"(addr));
}
__device__ __forceinline__ void mma_f16(float* d, const uint32_t* a, const uint32_t* b) {
    asm volatile(
        "mma.sync.aligned.m16n8k16.row.col.f32.f16.f16.f32 "
        "{%0,%1,%2,%3}, {%4,%5,%6,%7}, {%8,%9}, {%0,%1,%2,%3};"
        : "+f"(d[0]), "+f"(d[1]), "+f"(d[2]), "+f"(d[3])
        : "r"(a[0]), "r"(a[1]), "r"(a[2]), "r"(a[3]), "r"(b[0]), "r"(b[1]));
}
__device__ __forceinline__ float ex2_approx(float x) {
    float y;
    asm("ex2.approx.f32 %0, %1;" : "=f"(y) : "f"(x));
    return y;
}
__device__ __forceinline__ uint32_t pack_h2(float x0, float x1) {
    __half2 h = __floats2half2_rn(x0, x1);
    return *reinterpret_cast<uint32_t*>(&h);
}
// XOR swizzle for 128B-pitch rows (conflict-free ldmatrix, 8B-aligned cbyte)
__device__ __forceinline__ uint32_t swz(uint32_t r, uint32_t cbyte) {
    return r * 128 + (cbyte ^ ((r & 7) << 4));
}

// ---------------- kernel 1: W*64 -> fp16 --------------------------------------
__global__ void prep_w_kernel(const float* __restrict__ W) {
    int i = blockIdx.x * blockDim.x + threadIdx.x;   // float4 index
    float4 v = reinterpret_cast<const float4*>(W)[i];
    uint32_t h01 = pack_h2(v.x * WSCALE, v.y * WSCALE);
    uint32_t h23 = pack_h2(v.z * WSCALE, v.w * WSCALE);
    reinterpret_cast<uint2*>(g_w)[i] = make_uint2(h01, h23);
}

// ---------------- fused GEMM + softmax-attention (warp-specialized) ----------
// mix = fp16(A) @ fp16(W*64)^T / 64  -- single MMA term.
// CTA: 128 tokens x 192 cols, BK=128 per barrier period (2 x 64-wide subs).
// 640 threads = 20 warps:
//   warps 0-15  = consumers (4M x 4N, warp tile 32x48): LDSM + MMA only
//   warps 16-19 = producers: A LDG->fp16->STS (sub-tile pipelined), B cp.async
// A: 2 slots x 32KB (2 subs). B: 2 slots x 48KB (2 subs).
static constexpr int NSTEP     = HIDDEN / 128;    // 32 barrier periods
static constexpr int A_SUB     = 128 * 128;       // 16384 (64-k sub-tile)
static constexpr int A_STAGE   = 2 * A_SUB;       // 32768
static constexpr int B_OFF     = 2 * A_STAGE;     // 65536
static constexpr int B_SUB     = 192 * 128;       // 24576
static constexpr int B_STAGE   = 2 * B_SUB;       // 49152
static constexpr int GEMM_SMEM = B_OFF + 2 * B_STAGE;  // 163840
static constexpr int Q2_OFF    = 0;                     // 128*65*4 = 33280
static constexpr int KV_OFF    = 33280;                 // 128*66*8 = 67584

// named barrier ids: FULL = 1 + (k&1), FREE = 3 + (k&1)
__global__ void __launch_bounds__(640, 1)
gemm_fused_kernel(const float* __restrict__ A, float* __restrict__ out) {
    extern __shared__ char smem[];
    const uint32_t sb  = smem_u32(smem);
    const int tid   = threadIdx.x;
    const int wid   = tid >> 5;
    const int lid   = tid & 31;
    const int mbase = blockIdx.x * 128;
    const bool consumer = (wid < 16);

    float acc[2][6][4];
    #pragma unroll
    for (int mt = 0; mt < 2; ++mt)
        #pragma unroll
        for (int n = 0; n < 6; ++n)
            #pragma unroll
            for (int j = 0; j < 4; ++j) acc[mt][n][j] = 0.f;

    const int m0 = (wid & 3) * 32;    // consumer M offset (4 groups)
    const int n0 = (wid >> 2) * 48;   // consumer N offset (4 groups)

    // consumer ldmatrix lane addressing
    const uint32_t a_lrow = (uint32_t)(m0 + (lid & 15));
    const uint32_t a_lcol = (uint32_t)(((lid >> 4) & 1) * 16);
    const uint32_t b_lrow = (uint32_t)(n0 + (lid & 7) + ((lid >> 4) & 1) * 8);
    const uint32_t b_lcol = (uint32_t)(((lid >> 3) & 1) * 16);

    if (consumer) {
        // ============================ CONSUMER ============================
        uint32_t af[2][2][4], bf[2][3][4];   // double-buffered fragments

        // h = 0..7; sub-tile = h>>2, k16-within-sub = h&3
        auto load_frags = [&](uint32_t aBase, uint32_t bBase, int h, int buf) {
            const uint32_t aST = aBase + (uint32_t)(h >> 2) * A_SUB;
            const uint32_t bST = bBase + (uint32_t)(h >> 2) * B_SUB;
            const int hh = h & 3;
            #pragma unroll
            for (int mt = 0; mt < 2; ++mt)
                ldmatrix_x4(af[buf][mt],
                            aST + swz(a_lrow + mt * 16, a_lcol + hh * 32));
            #pragma unroll
            for (int g = 0; g < 3; ++g)
                ldmatrix_x4(bf[buf][g],
                            bST + swz(b_lrow + g * 16, b_lcol + hh * 32));
        };

        for (int kt = 0; kt < NSTEP; ++kt) {
            bar_sync(1 + (kt & 1));          // wait FULL(kt)
            bar_arrive(3 + ((kt + 1) & 1));  // release buffers of kt-1
            const uint32_t aBase = sb + (kt & 1) * A_STAGE;
            const uint32_t bBase = sb + B_OFF + (kt & 1) * B_STAGE;
            load_frags(aBase, bBase, 0, 0);
            #pragma unroll
            for (int h = 0; h < 8; ++h) {
                const int cur = h & 1;
                if (h < 7) load_frags(aBase, bBase, h + 1, cur ^ 1);
                // 12 independent MMAs on current buffer
                #pragma unroll
                for (int mt = 0; mt < 2; ++mt)
                    #pragma unroll
                    for (int n = 0; n < 6; ++n)
                        mma_f16(acc[mt][n], af[cur][mt],
                                bf[cur][n >> 1] + (n & 1) * 2);
            }
        }
    } else {
        // ============================ PRODUCER ============================
        const int pt = tid - 512;   // 0..127
        float4 va[16];              // A staging for one 64-k sub-tile

        // B cp.async for barrier period kt (both subs, 24 chunks per thread)
        auto cp_b = [&](int kt) {
            const uint32_t st = sb + B_OFF + (kt & 1) * B_STAGE;
            const char* wp = reinterpret_cast<const char*>(g_w);
            #pragma unroll
            for (int i = 0; i < 24; ++i) {
                int idx = pt + i * 128;           // 0..3071
                int sub = idx >= 1536;
                int j = idx - sub * 1536;         // 0..1535
                int r = j >> 3;                   // row 0..191
                uint32_t cbyte = (uint32_t)(j & 7) * 16;
                uint32_t dst = st + (uint32_t)sub * B_SUB + swz((uint32_t)r, cbyte);
                size_t soff = (size_t)r * (HIDDEN * 2) +
                              (size_t)kt * 256 + (size_t)sub * 128 + cbyte;
                cp_async16(dst, wp + soff);
            }
        };
        // issue A LDGs for (kt, sub) into va
        auto g2r_a = [&](int kt, int sub) {
            #pragma unroll
            for (int p = 0; p < 4; ++p) {
                int row = (pt >> 2) + 32 * p;
                const float4* Ag = reinterpret_cast<const float4*>(A) +
                                   (size_t)(mbase + row) * (HIDDEN / 4) +
                                   kt * 32 + sub * 16;
                #pragma unroll
                for (int i = 0; i < 4; ++i)
                    va[p * 4 + i] = Ag[(pt & 3) + 4 * i];
            }
        };
        // convert va -> fp16, store into (slot kt&1, sub)
        auto r2s_a = [&](int kt, int sub) {
            const uint32_t st = sb + (kt & 1) * A_STAGE + (uint32_t)sub * A_SUB;
            #pragma unroll
            for (int p = 0; p < 4; ++p) {
                int row = (pt >> 2) + 32 * p;
                #pragma unroll
                for (int i = 0; i < 4; ++i) {
                    float4 x = va[p * 4 + i];
                    uint32_t h01 = pack_h2(x.x, x.y);
                    uint32_t h23 = pack_h2(x.z, x.w);
                    uint32_t off = swz((uint32_t)row,
                                       (uint32_t)(8 * (pt & 3) + 32 * i));
                    sts64(st + off, h01, h23);
                }
            }
        };

        // prologue: fill slot 0 (both subs); preload (1,0)
        cp_b(0); cp_commit();
        g2r_a(0, 0); r2s_a(0, 0);
        g2r_a(0, 1); r2s_a(0, 1);
        g2r_a(1, 0);           // preload next period's sub0
        cp_wait<0>();          // B(0) complete
        bar_arrive(1 + 0);     // FULL(0)

        for (int kt = 0; kt < NSTEP - 1; ++kt) {
            bar_sync(3 + ((kt + 1) & 1));    // FREE: slot (kt+1) writable
            r2s_a(kt + 1, 0);                // store preloaded sub0
            g2r_a(kt + 1, 1);                // LDG sub1
            cp_b(kt + 1); cp_commit();       // B issue covers part of LDG wait
            r2s_a(kt + 1, 1);                // store sub1
            if (kt + 2 < NSTEP) g2r_a(kt + 2, 0);   // preload next sub0
            cp_wait<0>();
            bar_arrive(1 + ((kt + 1) & 1));  // FULL(kt+1)
        }
    }

    __syncthreads();   // all compute done; smem stages free for reuse

    // ---- scatter mix tile into reused smem (undo WSCALE here) ----
    float* q2  = reinterpret_cast<float*>(smem + Q2_OFF);   // [128][65]
    float* kvf = reinterpret_cast<float*>(smem + KV_OFF);   // [128][66] float2
    if (consumer) {
        const int d_row = lid >> 2, d_col = (lid & 3) * 2;
        #pragma unroll
        for (int mt = 0; mt < 2; ++mt) {
            #pragma unroll
            for (int n = 0; n < 6; ++n) {
                int t = m0 + mt * 16 + d_row;
                int c = n0 + n * 8 + d_col;
                #pragma unroll
                for (int j = 0; j < 4; ++j) {
                    int tt = t + (j >> 1) * 8;
                    int cc = c + (j & 1);
                    float v = acc[mt][n][j] * INV_WSCALE;
                    if (cc < 64)       q2[tt * 65 + cc] = v * LOG2E;
                    else if (cc < 128) kvf[(tt * 66 + cc - 64) * 2]      = v;
                    else               kvf[(tt * 66 + cc - 128) * 2 + 1] = v;
                }
            }
        }
    }
    __syncthreads();

    // ---- fused epilogue: per-token softmax attention (4 threads/token) ----
    if (tid < 512) {
        const int token = tid >> 2;   // 0..127
        const int g     = tid & 3;    // each owns 16 experts
        const float2* kvt = reinterpret_cast<const float2*>(kvf) + token * 66;
        const float*  q2t = q2 + token * 65;
        float* outt = out + (size_t)(mbase + token) * E;

        #pragma unroll 1
        for (int ei = 0; ei < 16; ei += 2) {
            int e0 = g * 16 + ei;
            float qa = q2t[e0], qb = q2t[e0 + 1];
            float Za = 0.f, Zb = 0.f, Sa = 0.f, Sb = 0.f;
            #pragma unroll 16
            for (int f = 0; f < E; ++f) {
                float2 p = kvt[f];
                float ta = ex2_approx(qa * p.x);
                float tb = ex2_approx(qb * p.x);
                Za += ta; Sa = fmaf(ta, p.y, Sa);
                Zb += tb; Sb = fmaf(tb, p.y, Sb);
            }
            outt[e0]     = __fdividef(Sa, Za);
            outt[e0 + 1] = __fdividef(Sb, Zb);
        }
    }
}

// ---------------- launch -----------------------------------------------------
extern "C" void kernel_launch(void* const* d_in, const int* in_sizes, int n_in,
                              void* d_out, int out_size) {
    const float* hidden = (const float*)d_in[0];   // [16384, 4096] f32
    const float* W      = (const float*)d_in[1];   // [192, 4096]  f32
    float* out          = (float*)d_out;           // [16384, 64]  f32

    cudaFuncSetAttribute(gemm_fused_kernel,
                         cudaFuncAttributeMaxDynamicSharedMemorySize, GEMM_SMEM);

    prep_w_kernel<<<(NE * HIDDEN / 4) / 256, 256>>>(W);
    gemm_fused_kernel<<<N_TOKENS / 128, 640, GEMM_SMEM>>>(hidden, out);
}

// round 16
// speedup vs baseline: 1.0719x; 1.0719x over previous
#include <cuda_runtime.h>
#include <cuda_fp16.h>
#include <cstdint>

#define N_TOKENS 16384
#define HIDDEN   4096
#define NE       192   // 3 * 64 experts
#define E        64
#define LOG2E    1.4426950408889634f
#define WSCALE   64.0f
#define INV_WSCALE (1.0f / 64.0f)

// ---------------- scratch ----------------------------------------------------
__device__ __half g_w[NE * HIDDEN];   // fp16(W * 64)

// ---------------- helpers ----------------------------------------------------
__device__ __forceinline__ uint32_t smem_u32(const void* p) {
    uint32_t a;
    asm("{ .reg .u64 t; cvta.to.shared.u64 t, %1; cvt.u32.u64 %0, t; }" : "=r"(a) : "l"(p));
    return a;
}
__device__ __forceinline__ void sts64(uint32_t addr, uint32_t a, uint32_t b) {
    asm volatile("st.shared.v2.b32 [%0], {%1, %2};" :: "r"(addr), "r"(a), "r"(b));
}
__device__ __forceinline__ void cp_async16(uint32_t dst, const void* src) {
    asm volatile("cp.async.cg.shared.global [%0], [%1], 16;" :: "r"(dst), "l"(src));
}
__device__ __forceinline__ void cp_commit() {
    asm volatile("cp.async.commit_group;" ::: "memory");
}
template <int N>
__device__ __forceinline__ void cp_wait() {
    asm volatile("cp.async.wait_group %0;" :: "n"(N) : "memory");
}
__device__ __forceinline__ void bar_sync(int id) {
    asm volatile("bar.sync %0, 512;" :: "r"(id) : "memory");
}
__device__ __forceinline__ void bar_arrive(int id) {
    asm volatile("bar.arrive %0, 512;" :: "r"(id) : "memory");
}
__device__ __forceinline__ void ldmatrix_x4(uint32_t* r, uint32_t addr) {
    asm volatile("ldmatrix.sync.aligned.m8n8.x4.shared.b16 {%0,%1,%2,%3}, [%4];"
                 : "=r"(r[0]), "=r"(r[1]), "=r"(r[2]), "=r"(r[3]) : "r"(addr));
}
__device__ __forceinline__ void mma_f16(float* d, const uint32_t* a, const uint32_t* b) {
    asm volatile(
        "mma.sync.aligned.m16n8k16.row.col.f32.f16.f16.f32 "
        "{%0,%1,%2,%3}, {%4,%5,%6,%7}, {%8,%9}, {%0,%1,%2,%3};"
        : "+f"(d[0]), "+f"(d[1]), "+f"(d[2]), "+f"(d[3])
        : "r"(a[0]), "r"(a[1]), "r"(a[2]), "r"(a[3]), "r"(b[0]), "r"(b[1]));
}
__device__ __forceinline__ float ex2_approx(float x) {
    float y;
    asm("ex2.approx.f32 %0, %1;" : "=f"(y) : "f"(x));
    return y;
}
__device__ __forceinline__ uint32_t pack_h2(float x0, float x1) {
    __half2 h = __floats2half2_rn(x0, x1);
    return *reinterpret_cast<uint32_t*>(&h);
}
// XOR swizzle for 128B-pitch rows (conflict-free ldmatrix, 8B-aligned cbyte)
__device__ __forceinline__ uint32_t swz(uint32_t r, uint32_t cbyte) {
    return r * 128 + (cbyte ^ ((r & 7) << 4));
}

// ---------------- kernel 1: W*64 -> fp16 --------------------------------------
__global__ void prep_w_kernel(const float* __restrict__ W) {
    int i = blockIdx.x * blockDim.x + threadIdx.x;   // float4 index
    float4 v = reinterpret_cast<const float4*>(W)[i];
    uint32_t h01 = pack_h2(v.x * WSCALE, v.y * WSCALE);
    uint32_t h23 = pack_h2(v.z * WSCALE, v.w * WSCALE);
    reinterpret_cast<uint2*>(g_w)[i] = make_uint2(h01, h23);
}

// ---------------- fused GEMM + softmax-attention (warp-specialized) ----------
// mix = fp16(A) @ fp16(W*64)^T / 64  -- single MMA term.
// CTA: 128 tokens x 192 cols, BK=128 per barrier period (2 x 64-wide subs).
// 512 threads:
//   warps 0-11  = consumers (4M x 3N, warp tile 32x64): LDSM + MMA only,
//                 each warp walks the 8 h-steps in a ROTATED order so LDSM
//                 bursts de-phase across the SM (uniform L1tex load)
//   warps 12-15 = producers: A LDG->fp16->STS (sub-tile pipelined), B cp.async
// A: 2 slots x 32KB (2 subs). B: 2 slots x 48KB (2 subs).
static constexpr int NSTEP     = HIDDEN / 128;    // 32 barrier periods
static constexpr int A_SUB     = 128 * 128;       // 16384 (64-k sub-tile)
static constexpr int A_STAGE   = 2 * A_SUB;       // 32768
static constexpr int B_OFF     = 2 * A_STAGE;     // 65536
static constexpr int B_SUB     = 192 * 128;       // 24576
static constexpr int B_STAGE   = 2 * B_SUB;       // 49152
static constexpr int GEMM_SMEM = B_OFF + 2 * B_STAGE;  // 163840
static constexpr int Q2_OFF    = 0;                     // 128*65*4 = 33280
static constexpr int KV_OFF    = 33280;                 // 128*66*8 = 67584

// named barrier ids: FULL = 1 + (k&1), FREE = 3 + (k&1)
__global__ void __launch_bounds__(512, 1)
gemm_fused_kernel(const float* __restrict__ A, float* __restrict__ out) {
    extern __shared__ char smem[];
    const uint32_t sb  = smem_u32(smem);
    const int tid   = threadIdx.x;
    const int wid   = tid >> 5;
    const int lid   = tid & 31;
    const int mbase = blockIdx.x * 128;
    const bool consumer = (wid < 12);

    float acc[2][8][4];
    #pragma unroll
    for (int mt = 0; mt < 2; ++mt)
        #pragma unroll
        for (int n = 0; n < 8; ++n)
            #pragma unroll
            for (int j = 0; j < 4; ++j) acc[mt][n][j] = 0.f;

    const int m0 = (wid & 3) * 32;    // consumer M offset (4 groups)
    const int n0 = (wid >> 2) * 64;   // consumer N offset (3 groups)

    // consumer ldmatrix lane addressing
    const uint32_t a_lrow = (uint32_t)(m0 + (lid & 15));
    const uint32_t a_lcol = (uint32_t)(((lid >> 4) & 1) * 16);
    const uint32_t b_lrow = (uint32_t)(n0 + (lid & 7) + ((lid >> 4) & 1) * 8);
    const uint32_t b_lcol = (uint32_t)(((lid >> 3) & 1) * 16);

    if (consumer) {
        // ============================ CONSUMER ============================
        uint32_t af[2][2][4], bf[2][4][4];   // double-buffered fragments
        const int hoff = (5 * wid) & 7;      // per-warp h-rotation (de-phase)

        // h = 0..7; sub-tile = h>>2, k16-within-sub = h&3
        auto load_frags = [&](uint32_t aBase, uint32_t bBase, int h, int buf) {
            const uint32_t aST = aBase + (uint32_t)(h >> 2) * A_SUB;
            const uint32_t bST = bBase + (uint32_t)(h >> 2) * B_SUB;
            const int hh = h & 3;
            #pragma unroll
            for (int mt = 0; mt < 2; ++mt)
                ldmatrix_x4(af[buf][mt],
                            aST + swz(a_lrow + mt * 16, a_lcol + hh * 32));
            #pragma unroll
            for (int g = 0; g < 4; ++g)
                ldmatrix_x4(bf[buf][g],
                            bST + swz(b_lrow + g * 16, b_lcol + hh * 32));
        };

        for (int kt = 0; kt < NSTEP; ++kt) {
            bar_sync(1 + (kt & 1));          // wait FULL(kt)
            bar_arrive(3 + ((kt + 1) & 1));  // release buffers of kt-1
            const uint32_t aBase = sb + (kt & 1) * A_STAGE;
            const uint32_t bBase = sb + B_OFF + (kt & 1) * B_STAGE;
            load_frags(aBase, bBase, hoff, 0);
            #pragma unroll
            for (int i = 0; i < 8; ++i) {
                const int cur = i & 1;
                if (i < 7)
                    load_frags(aBase, bBase, (i + 1 + hoff) & 7, cur ^ 1);
                // 16 independent MMAs on current buffer
                #pragma unroll
                for (int mt = 0; mt < 2; ++mt)
                    #pragma unroll
                    for (int n = 0; n < 8; ++n)
                        mma_f16(acc[mt][n], af[cur][mt],
                                bf[cur][n >> 1] + (n & 1) * 2);
            }
        }
    } else {
        // ============================ PRODUCER ============================
        const int pt = tid - 384;   // 0..127
        float4 va[16];              // A staging for one 64-k sub-tile

        // B cp.async for barrier period kt (both subs, 24 chunks per thread)
        auto cp_b = [&](int kt) {
            const uint32_t st = sb + B_OFF + (kt & 1) * B_STAGE;
            const char* wp = reinterpret_cast<const char*>(g_w);
            #pragma unroll
            for (int i = 0; i < 24; ++i) {
                int idx = pt + i * 128;           // 0..3071
                int sub = idx >= 1536;
                int j = idx - sub * 1536;         // 0..1535
                int r = j >> 3;                   // row 0..191
                uint32_t cbyte = (uint32_t)(j & 7) * 16;
                uint32_t dst = st + (uint32_t)sub * B_SUB + swz((uint32_t)r, cbyte);
                size_t soff = (size_t)r * (HIDDEN * 2) +
                              (size_t)kt * 256 + (size_t)sub * 128 + cbyte;
                cp_async16(dst, wp + soff);
            }
        };
        // issue A LDGs for (kt, sub) into va
        auto g2r_a = [&](int kt, int sub) {
            #pragma unroll
            for (int p = 0; p < 4; ++p) {
                int row = (pt >> 2) + 32 * p;
                const float4* Ag = reinterpret_cast<const float4*>(A) +
                                   (size_t)(mbase + row) * (HIDDEN / 4) +
                                   kt * 32 + sub * 16;
                #pragma unroll
                for (int i = 0; i < 4; ++i)
                    va[p * 4 + i] = Ag[(pt & 3) + 4 * i];
            }
        };
        // convert va -> fp16, store into (slot kt&1, sub)
        auto r2s_a = [&](int kt, int sub) {
            const uint32_t st = sb + (kt & 1) * A_STAGE + (uint32_t)sub * A_SUB;
            #pragma unroll
            for (int p = 0; p < 4; ++p) {
                int row = (pt >> 2) + 32 * p;
                #pragma unroll
                for (int i = 0; i < 4; ++i) {
                    float4 x = va[p * 4 + i];
                    uint32_t h01 = pack_h2(x.x, x.y);
                    uint32_t h23 = pack_h2(x.z, x.w);
                    uint32_t off = swz((uint32_t)row,
                                       (uint32_t)(8 * (pt & 3) + 32 * i));
                    sts64(st + off, h01, h23);
                }
            }
        };

        // prologue: fill slot 0 (both subs); preload (1,0)
        cp_b(0); cp_commit();
        g2r_a(0, 0); r2s_a(0, 0);
        g2r_a(0, 1); r2s_a(0, 1);
        g2r_a(1, 0);           // preload next period's sub0
        cp_wait<0>();          // B(0) complete
        bar_arrive(1 + 0);     // FULL(0)

        for (int kt = 0; kt < NSTEP - 1; ++kt) {
            bar_sync(3 + ((kt + 1) & 1));    // FREE: slot (kt+1) writable
            r2s_a(kt + 1, 0);                // store preloaded sub0
            g2r_a(kt + 1, 1);                // LDG sub1
            cp_b(kt + 1); cp_commit();       // B issue covers part of LDG wait
            r2s_a(kt + 1, 1);                // store sub1
            if (kt + 2 < NSTEP) g2r_a(kt + 2, 0);   // preload next sub0
            cp_wait<0>();
            bar_arrive(1 + ((kt + 1) & 1));  // FULL(kt+1)
        }
    }

    __syncthreads();   // all compute done; smem stages free for reuse

    // ---- scatter mix tile into reused smem (undo WSCALE here) ----
    float* q2  = reinterpret_cast<float*>(smem + Q2_OFF);   // [128][65]
    float* kvf = reinterpret_cast<float*>(smem + KV_OFF);   // [128][66] float2
    if (consumer) {
        const int d_row = lid >> 2, d_col = (lid & 3) * 2;
        #pragma unroll
        for (int mt = 0; mt < 2; ++mt) {
            #pragma unroll
            for (int n = 0; n < 8; ++n) {
                int t = m0 + mt * 16 + d_row;
                int c = n0 + n * 8 + d_col;
                #pragma unroll
                for (int j = 0; j < 4; ++j) {
                    int tt = t + (j >> 1) * 8;
                    int cc = c + (j & 1);
                    float v = acc[mt][n][j] * INV_WSCALE;
                    if (cc < 64)       q2[tt * 65 + cc] = v * LOG2E;
                    else if (cc < 128) kvf[(tt * 66 + cc - 64) * 2]      = v;
                    else               kvf[(tt * 66 + cc - 128) * 2 + 1] = v;
                }
            }
        }
    }
    __syncthreads();

    // ---- fused epilogue: per-token softmax attention (4 threads/token) ----
    const int token = tid >> 2;   // 0..127
    const int g     = tid & 3;    // each owns 16 experts
    const float2* kvt = reinterpret_cast<const float2*>(kvf) + token * 66;
    const float*  q2t = q2 + token * 65;
    float* outt = out + (size_t)(mbase + token) * E;

    #pragma unroll 1
    for (int ei = 0; ei < 16; ei += 2) {
        int e0 = g * 16 + ei;
        float qa = q2t[e0], qb = q2t[e0 + 1];
        float Za = 0.f, Zb = 0.f, Sa = 0.f, Sb = 0.f;
        #pragma unroll 16
        for (int f = 0; f < E; ++f) {
            float2 p = kvt[f];
            float ta = ex2_approx(qa * p.x);
            float tb = ex2_approx(qb * p.x);
            Za += ta; Sa = fmaf(ta, p.y, Sa);
            Zb += tb; Sb = fmaf(tb, p.y, Sb);
        }
        outt[e0]     = __fdividef(Sa, Za);
        outt[e0 + 1] = __fdividef(Sb, Zb);
    }
}

// ---------------- launch -----------------------------------------------------
extern "C" void kernel_launch(void* const* d_in, const int* in_sizes, int n_in,
                              void* d_out, int out_size) {
    const float* hidden = (const float*)d_in[0];   // [16384, 4096] f32
    const float* W      = (const float*)d_in[1];   // [192, 4096]  f32
    float* out          = (float*)d_out;           // [16384, 64]  f32

    cudaFuncSetAttribute(gemm_fused_kernel,
                         cudaFuncAttributeMaxDynamicSharedMemorySize, GEMM_SMEM);

    prep_w_kernel<<<(NE * HIDDEN / 4) / 256, 256>>>(W);
    gemm_fused_kernel<<<N_TOKENS / 128, 512, GEMM_SMEM>>>(hidden, out);
}